// round 9
// baseline (speedup 1.0000x reference)
#include <cuda_runtime.h>
#include <cstdint>

// SNN: fc1(21->100) -> 25-step Leaky -> fc2(100->10) -> Leaky
// Dense fused pass (R7 structure) with register-pressure fix:
//  - __launch_bounds__(128,2): 255-reg cap -> no mem1 spills
//  - reset recomputed from prev mem1 value (FSETP) -> no mask registers
//  - b2 pairs reloaded from SMEM each step
// Numerics bitwise-identical to passing kernels:
//  - cur1: acc=0, FMA k ascending, + b1 at end
//  - cur2: ascending-j chain; fma2(s,w,acc) with s in {0,1} == exact
//    add/identity -> bitwise == ordered column sum; + b2 pair-adds at end
//  - layer-1: mem = fma(beta,mem,cur); if(prev mem>1) mem = fsub(mem,1.0)
//  - layer-2: mem = fsub(fma(beta,mem,cur), prev_spk)

#define BETA    0.99f
#define NSTEPS  25
#define H1      100
#define H2      10
#define NIN     21
#define TPB     128

typedef unsigned long long u64;
typedef unsigned int u32;

__device__ __forceinline__ u64 fma2(u64 a, u64 b, u64 c) {
    u64 d;
    asm("fma.rn.f32x2 %0, %1, %2, %3;" : "=l"(d) : "l"(a), "l"(b), "l"(c));
    return d;
}
__device__ __forceinline__ u64 add2(u64 a, u64 b) {
    u64 d;
    asm("add.rn.f32x2 %0, %1, %2;" : "=l"(d) : "l"(a), "l"(b));
    return d;
}
__device__ __forceinline__ void unpack2(u64 v, float& a, float& b) {
    asm("mov.b64 {%0, %1}, %2;" : "=f"(a), "=f"(b) : "l"(v));
}
__device__ __forceinline__ u64 pack_dup(float s) {
    u64 r;
    asm("mov.b64 %0, {%1, %1};" : "=l"(r) : "f"(s));
    return r;
}

// dynamic smem layout (floats):
//   cur1_s : [25][TPB] float4  @ 0      (12800 floats, 51200 B)
//   W2s    : [100][12]         @ 12800  (1200 floats)
//   b2s    : [12]              @ 14000
//   W1s    : [100][24]         @ 14016
//   b1s    : [100]             @ 16416
#define OFF_CUR1 0
#define OFF_W2   12800
#define OFF_B2   14000
#define OFF_W1   14016
#define OFF_B1   16416
#define SMEM_FLOATS 16516
#define SMEM_BYTES (SMEM_FLOATS * 4)

__global__ __launch_bounds__(TPB, 2)
void snn_kernel(const float* __restrict__ x,
                const float* __restrict__ W1,
                const float* __restrict__ b1,
                const float* __restrict__ W2,
                const float* __restrict__ b2,
                float* __restrict__ out,
                int B)
{
    extern __shared__ __align__(16) float smem[];
    float* cur1_s = smem + OFF_CUR1;
    float* W2s    = smem + OFF_W2;
    float* b2s    = smem + OFF_B2;
    float* W1s    = smem + OFF_W1;
    float* b1s    = smem + OFF_B1;

    const int tid = threadIdx.x;

    for (int idx = tid; idx < H1 * NIN; idx += TPB)
        W1s[(idx / NIN) * 24 + (idx % NIN)] = W1[idx];
    for (int idx = tid; idx < H2 * H1; idx += TPB)
        W2s[(idx % H1) * 12 + (idx / H1)] = W2[idx];     // W2 is [10][100]
    for (int idx = tid; idx < H1; idx += TPB) {
        W2s[idx * 12 + 10] = 0.0f;                       // pad cols
        W2s[idx * 12 + 11] = 0.0f;
    }
    if (tid < H1) b1s[tid] = b1[tid];
    if (tid < 12) b2s[tid] = (tid < H2) ? b2[tid] : 0.0f;
    __syncthreads();

    const int sample = blockIdx.x * TPB + tid;
    if (sample >= B) return;

    // ---- x row ----
    float xr[NIN];
    const float* xrow = x + (size_t)sample * NIN;
#pragma unroll
    for (int i = 0; i < NIN; i++) xr[i] = __ldg(xrow + i);

    // ---- cur1 (all 100): acc=0, FMA k ascending, + b1; store to smem ----
#pragma unroll 1
    for (int g = 0; g < 25; g++) {
        float4 cv;
        float* cp = &cv.x;
#pragma unroll
        for (int i = 0; i < 4; i++) {
            const int j = g * 4 + i;
            const float* w = &W1s[j * 24];
            float acc = 0.0f;
#pragma unroll
            for (int k = 0; k < NIN; k++)
                acc = __fmaf_rn(xr[k], w[k], acc);
            cp[i] = __fadd_rn(acc, b1s[j]);
        }
        *(float4*)&cur1_s[(g * TPB + tid) * 4] = cv;
    }

    // ---- state ----
    float mem1[H1];
#pragma unroll
    for (int j = 0; j < H1; j++) mem1[j] = 0.0f;

    float mem2[H2], spk2[H2];
#pragma unroll
    for (int k = 0; k < H2; k++) { mem2[k] = 0.0f; spk2[k] = 0.0f; }

    float* spkout = out + (size_t)sample * H2;
    float* memout = spkout + (size_t)NSTEPS * B * H2;
    const size_t step_stride = (size_t)B * H2;

#pragma unroll 1
    for (int t = 0; t < NSTEPS; t++) {
        u64 a0 = 0ull, a1 = 0ull, a2 = 0ull, a3 = 0ull, a4 = 0ull;

#pragma unroll
        for (int g = 0; g < 25; g++) {
            float4 cv = *(const float4*)&cur1_s[(g * TPB + tid) * 4];
            const float* cp = &cv.x;
#pragma unroll
            for (int i = 0; i < 4; i++) {
                const int j = g * 4 + i;
                const float prev = mem1[j];
                float mv = __fmaf_rn(BETA, prev, cp[i]);
                if (prev > 1.0f) mv = __fsub_rn(mv, 1.0f);   // reset = prev spike
                mem1[j] = mv;
                const u64 s2 = pack_dup((mv > 1.0f) ? 1.0f : 0.0f);
                const float* w = &W2s[j * 12];
                ulonglong2 qa = *(const ulonglong2*)(w);
                ulonglong2 qb = *(const ulonglong2*)(w + 4);
                u64        qc = *(const u64*)(w + 8);
                a0 = fma2(s2, qa.x, a0);
                a1 = fma2(s2, qa.y, a1);
                a2 = fma2(s2, qb.x, a2);
                a3 = fma2(s2, qb.y, a3);
                a4 = fma2(s2, qc,   a4);
            }
        }

        {
            ulonglong2 bq = *(const ulonglong2*)&b2s[0];
            ulonglong2 br = *(const ulonglong2*)&b2s[4];
            u64        bs = *(const u64*)&b2s[8];
            a0 = add2(a0, bq.x);
            a1 = add2(a1, bq.y);
            a2 = add2(a2, br.x);
            a3 = add2(a3, br.y);
            a4 = add2(a4, bs);
        }

        float c[H2];
        unpack2(a0, c[0], c[1]);
        unpack2(a1, c[2], c[3]);
        unpack2(a2, c[4], c[5]);
        unpack2(a3, c[6], c[7]);
        unpack2(a4, c[8], c[9]);

        // ---- layer-2: mem = fl(fma(beta,mem,cur) - prev_spk) ----
#pragma unroll
        for (int k = 0; k < H2; k++) {
            float mv = __fsub_rn(__fmaf_rn(BETA, mem2[k], c[k]), spk2[k]);
            mem2[k] = mv;
            spk2[k] = (mv > 1.0f) ? 1.0f : 0.0f;
        }

        // ---- stores (float2, 8B aligned) ----
#pragma unroll
        for (int k = 0; k < 5; k++) {
            float2 sv; sv.x = spk2[2 * k]; sv.y = spk2[2 * k + 1];
            *(float2*)(spkout + 2 * k) = sv;
            float2 mv; mv.x = mem2[2 * k]; mv.y = mem2[2 * k + 1];
            *(float2*)(memout + 2 * k) = mv;
        }

        spkout += step_stride;
        memout += step_stride;
    }
}

extern "C" void kernel_launch(void* const* d_in, const int* in_sizes, int n_in,
                              void* d_out, int out_size) {
    const float* x  = (const float*)d_in[0];
    const float* W1 = (const float*)d_in[1];
    const float* b1 = (const float*)d_in[2];
    const float* W2 = (const float*)d_in[3];
    const float* b2 = (const float*)d_in[4];
    float* out = (float*)d_out;
    const int B = in_sizes[0] / NIN;

    static bool attr_set = false;  // idempotent attribute, not a work guard
    if (!attr_set) {
        cudaFuncSetAttribute(snn_kernel,
                             cudaFuncAttributeMaxDynamicSharedMemorySize,
                             SMEM_BYTES);
        attr_set = true;
    }

    const int grid = (B + TPB - 1) / TPB;
    snn_kernel<<<grid, TPB, SMEM_BYTES>>>(x, W1, b1, W2, b2, out, B);
}

// round 10
// speedup vs baseline: 1.0180x; 1.0180x over previous
#include <cuda_runtime.h>
#include <cstdint>

// SNN: fc1(21->100) -> 25-step Leaky -> fc2(100->10) -> Leaky
// Dense fused pass; per-sample state (cur1+mem1) lives in SMEM so the
// register live-set stays ~100 (no spills; that killed R7/R9).
// Numerics bitwise-identical to all passing kernels:
//  - cur1: acc=0, FMA k ascending, + b1 at end
//  - cur2: ascending-j chain; fma2(s,w,acc), s in {0,1} == exact add/identity
//    -> bitwise == ordered column sum; + b2 pair-adds at end
//  - layer-1: mem = fma(beta,mem,cur); if(prev mem>1) mem = fsub(mem,1.0)
//  - layer-2: mem = fsub(fma(beta,mem,cur), prev_spk)

#define BETA    0.99f
#define NSTEPS  25
#define H1      100
#define H2      10
#define NIN     21
#define TPB     128

typedef unsigned long long u64;
typedef unsigned int u32;

__device__ __forceinline__ u64 fma2(u64 a, u64 b, u64 c) {
    u64 d;
    asm("fma.rn.f32x2 %0, %1, %2, %3;" : "=l"(d) : "l"(a), "l"(b), "l"(c));
    return d;
}
__device__ __forceinline__ u64 add2(u64 a, u64 b) {
    u64 d;
    asm("add.rn.f32x2 %0, %1, %2;" : "=l"(d) : "l"(a), "l"(b));
    return d;
}
__device__ __forceinline__ void unpack2(u64 v, float& a, float& b) {
    asm("mov.b64 {%0, %1}, %2;" : "=f"(a), "=f"(b) : "l"(v));
}
__device__ __forceinline__ u64 pack_dup(float s) {
    u64 r;
    asm("mov.b64 %0, {%1, %1};" : "=l"(r) : "f"(s));
    return r;
}

// dynamic smem (floats):
//   state : [25][TPB][8]  @ 0       (25600 floats = 102400 B)
//           per (g,tid): cur1[4] at +0, mem1[4] at +4
//   wreg  : 2560 floats   @ 25600   (10240 B), time-multiplexed:
//           phase 1: W1temp[100][24] @ +0, b1temp[100] @ +2400
//           phase 2: W2s[100][12] @ +0 (cols 10,11 zero), b2s[12] @ +1216
#define OFF_STATE 0
#define OFF_WREG  25600
#define OFF_B2    (OFF_WREG + 1216)
#define SMEM_FLOATS (25600 + 2560)
#define SMEM_BYTES  (SMEM_FLOATS * 4)

__global__ __launch_bounds__(TPB, 2)
void snn_kernel(const float* __restrict__ x,
                const float* __restrict__ W1,
                const float* __restrict__ b1,
                const float* __restrict__ W2,
                const float* __restrict__ b2,
                float* __restrict__ out,
                int B)
{
    extern __shared__ __align__(16) float smem[];
    float* state = smem + OFF_STATE;
    float* wreg  = smem + OFF_WREG;

    const int tid = threadIdx.x;

    // ---- phase 1: stage W1/b1 into scratch ----
    for (int idx = tid; idx < H1 * NIN; idx += TPB)
        wreg[(idx / NIN) * 24 + (idx % NIN)] = W1[idx];
    if (tid < H1) wreg[2400 + tid] = b1[tid];
    __syncthreads();

    const int sample = blockIdx.x * TPB + tid;

    // ---- cur1: acc=0, FMA k ascending, + b1; write cur1+zero mem1 ----
    if (sample < B) {
        float xr[NIN];
        const float* xrow = x + (size_t)sample * NIN;
#pragma unroll
        for (int i = 0; i < NIN; i++) xr[i] = __ldg(xrow + i);

#pragma unroll 1
        for (int g = 0; g < 25; g++) {
            float4 cv;
            float* cp = &cv.x;
#pragma unroll
            for (int i = 0; i < 4; i++) {
                const int j = g * 4 + i;
                const float* w = &wreg[j * 24];
                float acc = 0.0f;
#pragma unroll
                for (int k = 0; k < NIN; k++)
                    acc = __fmaf_rn(xr[k], w[k], acc);
                cp[i] = __fadd_rn(acc, wreg[2400 + j]);
            }
            float* sb = &state[(g * TPB + tid) * 8];
            *(float4*)(sb)     = cv;
            *(float4*)(sb + 4) = make_float4(0.f, 0.f, 0.f, 0.f);
        }
    }
    __syncthreads();   // all reads of W1temp done

    // ---- phase 2: stage W2 (transposed, padded) + b2 into scratch ----
    for (int idx = tid; idx < H2 * H1; idx += TPB)
        wreg[(idx % H1) * 12 + (idx / H1)] = W2[idx];    // W2 is [10][100]
    for (int idx = tid; idx < H1; idx += TPB) {
        wreg[idx * 12 + 10] = 0.0f;
        wreg[idx * 12 + 11] = 0.0f;
    }
    if (tid < 12) smem[OFF_B2 + tid] = (tid < H2) ? b2[tid] : 0.0f;
    __syncthreads();

    if (sample >= B) return;

    float mem2[H2], spk2[H2];
#pragma unroll
    for (int k = 0; k < H2; k++) { mem2[k] = 0.0f; spk2[k] = 0.0f; }

    float* spkout = out + (size_t)sample * H2;
    float* memout = spkout + (size_t)NSTEPS * B * H2;
    const size_t step_stride = (size_t)B * H2;

#pragma unroll 1
    for (int t = 0; t < NSTEPS; t++) {
        u64 a0 = 0ull, a1 = 0ull, a2 = 0ull, a3 = 0ull, a4 = 0ull;

#pragma unroll
        for (int g = 0; g < 25; g++) {
            float* sb = &state[(g * TPB + tid) * 8];
            float4 cv = *(const float4*)(sb);
            float4 mvv = *(const float4*)(sb + 4);
            const float* cp = &cv.x;
            float* mp = &mvv.x;
#pragma unroll
            for (int i = 0; i < 4; i++) {
                const int j = g * 4 + i;
                const float prev = mp[i];
                float mv = __fmaf_rn(BETA, prev, cp[i]);
                if (prev > 1.0f) mv = __fsub_rn(mv, 1.0f);   // reset = prev spike
                mp[i] = mv;
                const u64 s2 = pack_dup((mv > 1.0f) ? 1.0f : 0.0f);
                const float* w = &wreg[j * 12];
                ulonglong2 qa = *(const ulonglong2*)(w);
                ulonglong2 qb = *(const ulonglong2*)(w + 4);
                a0 = fma2(s2, qa.x, a0);
                a1 = fma2(s2, qa.y, a1);
                a2 = fma2(s2, qb.x, a2);
                a3 = fma2(s2, qb.y, a3);
                a4 = fma2(s2, *(const u64*)(w + 8), a4);
            }
            *(float4*)(sb + 4) = mvv;
        }

        {
            ulonglong2 bq = *(const ulonglong2*)&smem[OFF_B2];
            ulonglong2 br = *(const ulonglong2*)&smem[OFF_B2 + 4];
            u64        bs = *(const u64*)&smem[OFF_B2 + 8];
            a0 = add2(a0, bq.x);
            a1 = add2(a1, bq.y);
            a2 = add2(a2, br.x);
            a3 = add2(a3, br.y);
            a4 = add2(a4, bs);
        }

        float c[H2];
        unpack2(a0, c[0], c[1]);
        unpack2(a1, c[2], c[3]);
        unpack2(a2, c[4], c[5]);
        unpack2(a3, c[6], c[7]);
        unpack2(a4, c[8], c[9]);

        // ---- layer-2: mem = fl(fma(beta,mem,cur) - prev_spk) ----
#pragma unroll
        for (int k = 0; k < H2; k++) {
            float mv = __fsub_rn(__fmaf_rn(BETA, mem2[k], c[k]), spk2[k]);
            mem2[k] = mv;
            spk2[k] = (mv > 1.0f) ? 1.0f : 0.0f;
        }

        // ---- stores (float2, 8B aligned) ----
#pragma unroll
        for (int k = 0; k < 5; k++) {
            float2 sv; sv.x = spk2[2 * k]; sv.y = spk2[2 * k + 1];
            *(float2*)(spkout + 2 * k) = sv;
            float2 mv; mv.x = mem2[2 * k]; mv.y = mem2[2 * k + 1];
            *(float2*)(memout + 2 * k) = mv;
        }

        spkout += step_stride;
        memout += step_stride;
    }
}

extern "C" void kernel_launch(void* const* d_in, const int* in_sizes, int n_in,
                              void* d_out, int out_size) {
    const float* x  = (const float*)d_in[0];
    const float* W1 = (const float*)d_in[1];
    const float* b1 = (const float*)d_in[2];
    const float* W2 = (const float*)d_in[3];
    const float* b2 = (const float*)d_in[4];
    float* out = (float*)d_out;
    const int B = in_sizes[0] / NIN;

    static bool attr_set = false;  // idempotent attribute, not a work guard
    if (!attr_set) {
        cudaFuncSetAttribute(snn_kernel,
                             cudaFuncAttributeMaxDynamicSharedMemorySize,
                             SMEM_BYTES);
        attr_set = true;
    }

    const int grid = (B + TPB - 1) / TPB;
    snn_kernel<<<grid, TPB, SMEM_BYTES>>>(x, W1, b1, W2, b2, out, B);
}

// round 13
// speedup vs baseline: 6.4870x; 6.3723x over previous
#include <cuda_runtime.h>
#include <cstdint>

// SNN: fc1(21->100) -> 25-step Leaky -> fc2(100->10) -> Leaky
// Dense fused pass; per-sample state (cur1+mem1) in SMEM.
// KEY FIX vs R10: group loop is `#pragma unroll 2` (8 j / iter) so ptxas
// cannot front-batch the whole step's loads -> live set ~90 regs, no spills.
// Numerics bitwise-identical to all passing kernels:
//  - cur1: acc=0, FMA k ascending, + b1 at end
//  - cur2: ascending-j chain; fma2(s,w,acc), s in {0,1} == exact add/identity
//    -> bitwise == ordered column sum; + b2 pair-adds at end
//  - layer-1: mem = fma(beta,mem,cur); if(prev mem>1) mem = fsub(mem,1.0)
//  - layer-2: mem = fsub(fma(beta,mem,cur), prev_spk)

#define BETA    0.99f
#define NSTEPS  25
#define H1      100
#define H2      10
#define NIN     21
#define TPB     128

typedef unsigned long long u64;
typedef unsigned int u32;

__device__ __forceinline__ u64 fma2(u64 a, u64 b, u64 c) {
    u64 d;
    asm("fma.rn.f32x2 %0, %1, %2, %3;" : "=l"(d) : "l"(a), "l"(b), "l"(c));
    return d;
}
__device__ __forceinline__ u64 add2(u64 a, u64 b) {
    u64 d;
    asm("add.rn.f32x2 %0, %1, %2;" : "=l"(d) : "l"(a), "l"(b));
    return d;
}
__device__ __forceinline__ void unpack2(u64 v, float& a, float& b) {
    asm("mov.b64 {%0, %1}, %2;" : "=f"(a), "=f"(b) : "l"(v));
}

// dynamic smem (floats):
//   state : [25][TPB][8]  @ 0       (25600 floats = 102400 B)
//           per (g,tid): cur1[4] at +0, mem1[4] at +4
//   wreg  : 2560 floats   @ 25600   (10240 B), time-multiplexed:
//           phase 1: W1temp[100][24] @ +0, b1temp[100] @ +2400
//           phase 2: W2s[100][12] @ +0 (cols 10,11 zero), b2s[12] @ +1216
#define OFF_STATE 0
#define OFF_WREG  25600
#define OFF_B2    (OFF_WREG + 1216)
#define SMEM_FLOATS (25600 + 2560)
#define SMEM_BYTES  (SMEM_FLOATS * 4)

__global__ __launch_bounds__(TPB, 2)
void snn_kernel(const float* __restrict__ x,
                const float* __restrict__ W1,
                const float* __restrict__ b1,
                const float* __restrict__ W2,
                const float* __restrict__ b2,
                float* __restrict__ out,
                int B)
{
    extern __shared__ __align__(16) float smem[];
    float* state = smem + OFF_STATE;
    float* wreg  = smem + OFF_WREG;

    const int tid = threadIdx.x;

    // ---- phase 1: stage W1/b1 into scratch ----
    for (int idx = tid; idx < H1 * NIN; idx += TPB)
        wreg[(idx / NIN) * 24 + (idx % NIN)] = W1[idx];
    if (tid < H1) wreg[2400 + tid] = b1[tid];
    __syncthreads();

    const int sample = blockIdx.x * TPB + tid;

    // ---- cur1: acc=0, FMA k ascending, + b1; write cur1 + zero mem1 ----
    if (sample < B) {
        float xr[NIN];
        const float* xrow = x + (size_t)sample * NIN;
#pragma unroll
        for (int i = 0; i < NIN; i++) xr[i] = __ldg(xrow + i);

#pragma unroll 1
        for (int g = 0; g < 25; g++) {
            float4 cv;
            float* cp = &cv.x;
#pragma unroll
            for (int i = 0; i < 4; i++) {
                const int j = g * 4 + i;
                const float* w = &wreg[j * 24];
                float acc = 0.0f;
#pragma unroll
                for (int k = 0; k < NIN; k++)
                    acc = __fmaf_rn(xr[k], w[k], acc);
                cp[i] = __fadd_rn(acc, wreg[2400 + j]);
            }
            float* sb = &state[(g * TPB + tid) * 8];
            *(float4*)(sb)     = cv;
            *(float4*)(sb + 4) = make_float4(0.f, 0.f, 0.f, 0.f);
        }
    }
    __syncthreads();   // all reads of W1temp done

    // ---- phase 2: stage W2 (transposed, padded) + b2 into scratch ----
    for (int idx = tid; idx < H2 * H1; idx += TPB)
        wreg[(idx % H1) * 12 + (idx / H1)] = W2[idx];    // W2 is [10][100]
    for (int idx = tid; idx < H1; idx += TPB) {
        wreg[idx * 12 + 10] = 0.0f;
        wreg[idx * 12 + 11] = 0.0f;
    }
    if (tid < 12) smem[OFF_B2 + tid] = (tid < H2) ? b2[tid] : 0.0f;
    __syncthreads();

    if (sample >= B) return;

    const u64 ONE2 = 0x3f8000003f800000ull;   // {1.0f, 1.0f}

    float mem2[H2], spk2[H2];
#pragma unroll
    for (int k = 0; k < H2; k++) { mem2[k] = 0.0f; spk2[k] = 0.0f; }

    float* spkout = out + (size_t)sample * H2;
    float* memout = spkout + (size_t)NSTEPS * B * H2;
    const size_t step_stride = (size_t)B * H2;

#pragma unroll 1
    for (int t = 0; t < NSTEPS; t++) {
        u64 a0 = 0ull, a1 = 0ull, a2 = 0ull, a3 = 0ull, a4 = 0ull;

#pragma unroll 2
        for (int g = 0; g < 25; g++) {
            float* sb = &state[(g * TPB + tid) * 8];
            float4 cv  = *(const float4*)(sb);
            float4 mvv = *(const float4*)(sb + 4);
            const float* cp = &cv.x;
            float* mp = &mvv.x;
#pragma unroll
            for (int i = 0; i < 4; i++) {
                const int j = g * 4 + i;
                const float prev = mp[i];
                float mv = __fmaf_rn(BETA, prev, cp[i]);
                if (prev > 1.0f) mv = __fsub_rn(mv, 1.0f);   // reset = prev spike
                mp[i] = mv;
                const u64 s2 = (mv > 1.0f) ? ONE2 : 0ull;
                const float* w = &wreg[j * 12];
                ulonglong2 qa = *(const ulonglong2*)(w);
                ulonglong2 qb = *(const ulonglong2*)(w + 4);
                a0 = fma2(s2, qa.x, a0);
                a1 = fma2(s2, qa.y, a1);
                a2 = fma2(s2, qb.x, a2);
                a3 = fma2(s2, qb.y, a3);
                a4 = fma2(s2, *(const u64*)(w + 8), a4);
            }
            *(float4*)(sb + 4) = mvv;
        }

        {
            ulonglong2 bq = *(const ulonglong2*)&smem[OFF_B2];
            ulonglong2 br = *(const ulonglong2*)&smem[OFF_B2 + 4];
            u64        bs = *(const u64*)&smem[OFF_B2 + 8];
            a0 = add2(a0, bq.x);
            a1 = add2(a1, bq.y);
            a2 = add2(a2, br.x);
            a3 = add2(a3, br.y);
            a4 = add2(a4, bs);
        }

        float c[H2];
        unpack2(a0, c[0], c[1]);
        unpack2(a1, c[2], c[3]);
        unpack2(a2, c[4], c[5]);
        unpack2(a3, c[6], c[7]);
        unpack2(a4, c[8], c[9]);

        // ---- layer-2: mem = fl(fma(beta,mem,cur) - prev_spk) ----
#pragma unroll
        for (int k = 0; k < H2; k++) {
            float mv = __fsub_rn(__fmaf_rn(BETA, mem2[k], c[k]), spk2[k]);
            mem2[k] = mv;
            spk2[k] = (mv > 1.0f) ? 1.0f : 0.0f;
        }

        // ---- stores (float2, 8B aligned) ----
#pragma unroll
        for (int k = 0; k < 5; k++) {
            float2 sv; sv.x = spk2[2 * k]; sv.y = spk2[2 * k + 1];
            *(float2*)(spkout + 2 * k) = sv;
            float2 mv; mv.x = mem2[2 * k]; mv.y = mem2[2 * k + 1];
            *(float2*)(memout + 2 * k) = mv;
        }

        spkout += step_stride;
        memout += step_stride;
    }
}

extern "C" void kernel_launch(void* const* d_in, const int* in_sizes, int n_in,
                              void* d_out, int out_size) {
    const float* x  = (const float*)d_in[0];
    const float* W1 = (const float*)d_in[1];
    const float* b1 = (const float*)d_in[2];
    const float* W2 = (const float*)d_in[3];
    const float* b2 = (const float*)d_in[4];
    float* out = (float*)d_out;
    const int B = in_sizes[0] / NIN;

    static bool attr_set = false;  // idempotent attribute, not a work guard
    if (!attr_set) {
        cudaFuncSetAttribute(snn_kernel,
                             cudaFuncAttributeMaxDynamicSharedMemorySize,
                             SMEM_BYTES);
        attr_set = true;
    }

    const int grid = (B + TPB - 1) / TPB;
    snn_kernel<<<grid, TPB, SMEM_BYTES>>>(x, W1, b1, W2, b2, out, B);
}

// round 14
// speedup vs baseline: 12.4845x; 1.9245x over previous
#include <cuda_runtime.h>
#include <cstdint>

// SNN: fc1(21->100) -> 25-step Leaky -> fc2(100->10) -> Leaky
// t-CHUNKED dense pass: 5 timesteps per sweep over j. Per j per chunk:
// W2 row loaded once, state loaded/stored once, 5 membrane updates in regs,
// spikes fma2'd into 25 accumulators (5 t x 5 output-pairs).
// Chain order: j ascending for every t -> bitwise identical to R13 (passing).
// Numerics:
//  - cur1: acc=0, FMA k ascending, + b1 at end
//  - cur2: fma2(s,w,acc), s in {0,1} == exact add/identity, ascending j;
//    + b2 pair-adds at end
//  - layer-1: mem = fma(beta,mem,cur); if(prev mem>1) mem = fsub(mem,1.0)
//  - layer-2: mem = fsub(fma(beta,mem,cur), prev_spk)

#define BETA    0.99f
#define NSTEPS  25
#define TCHUNK  5
#define NCHUNK  5
#define H1      100
#define H2      10
#define NIN     21
#define TPB     128

typedef unsigned long long u64;
typedef unsigned int u32;

__device__ __forceinline__ u64 fma2(u64 a, u64 b, u64 c) {
    u64 d;
    asm("fma.rn.f32x2 %0, %1, %2, %3;" : "=l"(d) : "l"(a), "l"(b), "l"(c));
    return d;
}
__device__ __forceinline__ u64 add2(u64 a, u64 b) {
    u64 d;
    asm("add.rn.f32x2 %0, %1, %2;" : "=l"(d) : "l"(a), "l"(b));
    return d;
}
__device__ __forceinline__ void unpack2(u64 v, float& a, float& b) {
    asm("mov.b64 {%0, %1}, %2;" : "=f"(a), "=f"(b) : "l"(v));
}

// dynamic smem (floats):
//   state : [25][TPB][8]  @ 0       (25600 floats = 102400 B)
//           per (g,tid): cur1[4] at +0, mem1[4] at +4
//   wreg  : 2560 floats   @ 25600   (10240 B), time-multiplexed:
//           phase 1: W1temp[100][24] @ +0, b1temp[100] @ +2400
//           phase 2: W2s[100][12] @ +0 (cols 10,11 zero), b2s[12] @ +1216
#define OFF_STATE 0
#define OFF_WREG  25600
#define OFF_B2    (OFF_WREG + 1216)
#define SMEM_FLOATS (25600 + 2560)
#define SMEM_BYTES  (SMEM_FLOATS * 4)

__global__ __launch_bounds__(TPB, 2)
void snn_kernel(const float* __restrict__ x,
                const float* __restrict__ W1,
                const float* __restrict__ b1,
                const float* __restrict__ W2,
                const float* __restrict__ b2,
                float* __restrict__ out,
                int B)
{
    extern __shared__ __align__(16) float smem[];
    float* state = smem + OFF_STATE;
    float* wreg  = smem + OFF_WREG;

    const int tid = threadIdx.x;

    // ---- phase 1: stage W1/b1 into scratch ----
    for (int idx = tid; idx < H1 * NIN; idx += TPB)
        wreg[(idx / NIN) * 24 + (idx % NIN)] = W1[idx];
    if (tid < H1) wreg[2400 + tid] = b1[tid];
    __syncthreads();

    const int sample = blockIdx.x * TPB + tid;

    // ---- cur1: acc=0, FMA k ascending, + b1; write cur1 + zero mem1 ----
    if (sample < B) {
        float xr[NIN];
        const float* xrow = x + (size_t)sample * NIN;
#pragma unroll
        for (int i = 0; i < NIN; i++) xr[i] = __ldg(xrow + i);

#pragma unroll 1
        for (int g = 0; g < 25; g++) {
            float4 cv;
            float* cp = &cv.x;
#pragma unroll
            for (int i = 0; i < 4; i++) {
                const int j = g * 4 + i;
                const float* w = &wreg[j * 24];
                float acc = 0.0f;
#pragma unroll
                for (int k = 0; k < NIN; k++)
                    acc = __fmaf_rn(xr[k], w[k], acc);
                cp[i] = __fadd_rn(acc, wreg[2400 + j]);
            }
            float* sb = &state[(g * TPB + tid) * 8];
            *(float4*)(sb)     = cv;
            *(float4*)(sb + 4) = make_float4(0.f, 0.f, 0.f, 0.f);
        }
    }
    __syncthreads();   // all reads of W1temp done

    // ---- phase 2: stage W2 (transposed, padded) + b2 into scratch ----
    for (int idx = tid; idx < H2 * H1; idx += TPB)
        wreg[(idx % H1) * 12 + (idx / H1)] = W2[idx];    // W2 is [10][100]
    for (int idx = tid; idx < H1; idx += TPB) {
        wreg[idx * 12 + 10] = 0.0f;
        wreg[idx * 12 + 11] = 0.0f;
    }
    if (tid < 12) smem[OFF_B2 + tid] = (tid < H2) ? b2[tid] : 0.0f;
    __syncthreads();

    if (sample >= B) return;

    const u64 ONE2 = 0x3f8000003f800000ull;   // {1.0f, 1.0f}

    float mem2[H2], spk2[H2];
#pragma unroll
    for (int k = 0; k < H2; k++) { mem2[k] = 0.0f; spk2[k] = 0.0f; }

    float* spkout = out + (size_t)sample * H2;
    float* memout = spkout + (size_t)NSTEPS * B * H2;
    const size_t step_stride = (size_t)B * H2;

#pragma unroll 1
    for (int c = 0; c < NCHUNK; c++) {
        u64 acc[TCHUNK][5];
#pragma unroll
        for (int tt = 0; tt < TCHUNK; tt++)
#pragma unroll
            for (int p = 0; p < 5; p++) acc[tt][p] = 0ull;

#pragma unroll 1
        for (int g = 0; g < 25; g++) {
            float* sb = &state[(g * TPB + tid) * 8];
            float4 cv  = *(const float4*)(sb);
            float4 mvv = *(const float4*)(sb + 4);
            const float* cp = &cv.x;
            float* mp = &mvv.x;
#pragma unroll
            for (int i = 0; i < 4; i++) {
                const int j = g * 4 + i;
                const float* w = &wreg[j * 12];
                ulonglong2 qa = *(const ulonglong2*)(w);
                ulonglong2 qb = *(const ulonglong2*)(w + 4);
                u64        qc = *(const u64*)(w + 8);
                float prev = mp[i];
                const float cur = cp[i];
#pragma unroll
                for (int tt = 0; tt < TCHUNK; tt++) {
                    float mv = __fmaf_rn(BETA, prev, cur);
                    if (prev > 1.0f) mv = __fsub_rn(mv, 1.0f);  // reset = prev spike
                    const u64 s2 = (mv > 1.0f) ? ONE2 : 0ull;
                    acc[tt][0] = fma2(s2, qa.x, acc[tt][0]);
                    acc[tt][1] = fma2(s2, qa.y, acc[tt][1]);
                    acc[tt][2] = fma2(s2, qb.x, acc[tt][2]);
                    acc[tt][3] = fma2(s2, qb.y, acc[tt][3]);
                    acc[tt][4] = fma2(s2, qc,   acc[tt][4]);
                    prev = mv;
                }
                mp[i] = prev;
            }
            *(float4*)(sb + 4) = mvv;
        }

        // ---- chunk epilogue: bias, layer-2 recurrence, stores ----
        ulonglong2 bq = *(const ulonglong2*)&smem[OFF_B2];
        ulonglong2 br = *(const ulonglong2*)&smem[OFF_B2 + 4];
        u64        bs = *(const u64*)&smem[OFF_B2 + 8];

#pragma unroll
        for (int tt = 0; tt < TCHUNK; tt++) {
            u64 a0 = add2(acc[tt][0], bq.x);
            u64 a1 = add2(acc[tt][1], bq.y);
            u64 a2 = add2(acc[tt][2], br.x);
            u64 a3 = add2(acc[tt][3], br.y);
            u64 a4 = add2(acc[tt][4], bs);

            float cc[H2];
            unpack2(a0, cc[0], cc[1]);
            unpack2(a1, cc[2], cc[3]);
            unpack2(a2, cc[4], cc[5]);
            unpack2(a3, cc[6], cc[7]);
            unpack2(a4, cc[8], cc[9]);

#pragma unroll
            for (int k = 0; k < H2; k++) {
                float mv = __fsub_rn(__fmaf_rn(BETA, mem2[k], cc[k]), spk2[k]);
                mem2[k] = mv;
                spk2[k] = (mv > 1.0f) ? 1.0f : 0.0f;
            }

            float* so = spkout + (size_t)(c * TCHUNK + tt) * step_stride;
            float* mo = memout + (size_t)(c * TCHUNK + tt) * step_stride;
#pragma unroll
            for (int k = 0; k < 5; k++) {
                float2 sv; sv.x = spk2[2 * k]; sv.y = spk2[2 * k + 1];
                *(float2*)(so + 2 * k) = sv;
                float2 mv; mv.x = mem2[2 * k]; mv.y = mem2[2 * k + 1];
                *(float2*)(mo + 2 * k) = mv;
            }
        }
    }
}

extern "C" void kernel_launch(void* const* d_in, const int* in_sizes, int n_in,
                              void* d_out, int out_size) {
    const float* x  = (const float*)d_in[0];
    const float* W1 = (const float*)d_in[1];
    const float* b1 = (const float*)d_in[2];
    const float* W2 = (const float*)d_in[3];
    const float* b2 = (const float*)d_in[4];
    float* out = (float*)d_out;
    const int B = in_sizes[0] / NIN;

    static bool attr_set = false;  // idempotent attribute, not a work guard
    if (!attr_set) {
        cudaFuncSetAttribute(snn_kernel,
                             cudaFuncAttributeMaxDynamicSharedMemorySize,
                             SMEM_BYTES);
        attr_set = true;
    }

    const int grid = (B + TPB - 1) / TPB;
    snn_kernel<<<grid, TPB, SMEM_BYTES>>>(x, W1, b1, W2, b2, out, B);
}